// round 1
// baseline (speedup 1.0000x reference)
#include <cuda_runtime.h>
#include <cstdint>

#define B 1024
#define T 128
#define INP 5
#define H 100
#define G4 400   // 4*H

// ---------------- scratch (device globals; no runtime allocation) ----------
__device__ float g_h0 [B * T * 2 * H];   // [b][t][200]  layer0 output (fwd|bwd)
__device__ float g_xg1[B * T * G4];      // [b*T+t][400] layer1-fwd input gates (+biases)
__device__ float g_h1f[B * H];           // layer1-fwd final hidden

typedef unsigned long long u64;

// ---------------- packed fp32x2 helpers ------------------------------------
__device__ __forceinline__ u64 pk2(float a, float b) {
    u64 r; asm("mov.b64 %0, {%1,%2};" : "=l"(r) : "f"(a), "f"(b)); return r;
}
__device__ __forceinline__ void upk2(u64 v, float& a, float& b) {
    asm("mov.b64 {%0,%1}, %2;" : "=f"(a), "=f"(b) : "l"(v));
}
__device__ __forceinline__ u64 ffma2(u64 a, u64 b, u64 c) {
    asm("fma.rn.f32x2 %0, %1, %2, %0;" : "+l"(c) : "l"(a), "l"(b)); return c;
}
__device__ __forceinline__ float sigmoidf_(float x) {
    return 1.0f / (1.0f + __expf(-x));
}

// ============================================================================
// Kernel 1: layer0, both directions. grid=128 (dir*64+chunk), block=256.
// Each CTA: 16 batch rows, whole T loop, W_hh^T resident in SMEM.
// Thread (grp=tid>>7, jj=tid&127, active jj<100) owns state jj for 8 batches
// (4 f32x2 pairs); gates computed packed 2-batches-per-lane.
// smem floats: WHH_T 40000 | WIH_T 2000 | BIAS 400 | H2 100*9*2 | X2 5*8*2
// ============================================================================
#define L0_NB    16
#define L0_PAIRS 8
#define L0_PAD   9
#define L0_SMEMF (40000 + 2000 + 400 + 100*L0_PAD*2 + INP*L0_PAIRS*2)

__global__ void __launch_bounds__(256, 1) lstm_layer0(
    const float* __restrict__ x,
    const float* __restrict__ wih_f, const float* __restrict__ whh_f,
    const float* __restrict__ bih_f, const float* __restrict__ bhh_f,
    const float* __restrict__ wih_b, const float* __restrict__ whh_b,
    const float* __restrict__ bih_b, const float* __restrict__ bhh_b)
{
    extern __shared__ float sm[];
    float* whh_t = sm;                          // [100][400] (k-major)
    float* wihT  = sm + 40000;                  // [5][400]
    float* bias  = sm + 42000;                  // [400]  (b_ih + b_hh)
    float* h2f   = sm + 42400;                  // float2 [100][9]
    float* x2f   = sm + 42400 + 100*L0_PAD*2;   // float2 [5][8]

    const int tid = threadIdx.x;
    const int dir = blockIdx.x >> 6;
    const int b0  = (blockIdx.x & 63) * L0_NB;
    const float* wih = dir ? wih_b : wih_f;
    const float* whh = dir ? whh_b : whh_f;
    const float* bih = dir ? bih_b : bih_f;
    const float* bhh = dir ? bhh_b : bhh_f;

    for (int i = tid; i < 40000; i += 256) {
        int g = i / 100, k = i - g * 100;
        whh_t[k * 400 + g] = whh[i];
    }
    for (int i = tid; i < 2000; i += 256) {
        int g = i / 5, d = i - g * 5;
        wihT[d * 400 + g] = wih[i];
    }
    for (int i = tid; i < 400; i += 256) bias[i] = bih[i] + bhh[i];
    for (int i = tid; i < 100 * L0_PAD * 2; i += 256) h2f[i] = 0.f;

    const int  jj  = tid & 127;
    const int  grp = tid >> 7;
    const bool act = (jj < H);
    float c_reg[8];
    #pragma unroll
    for (int i = 0; i < 8; i++) c_reg[i] = 0.f;

    const u64* h2u = (const u64*)h2f;
    const u64* x2u = (const u64*)x2f;

    __syncthreads();

    for (int ts = 0; ts < T; ts++) {
        const int t = dir ? (T - 1 - ts) : ts;

        if (tid < L0_NB * INP) {
            int bl = tid / INP, d = tid - bl * INP;
            x2f[(d * L0_PAIRS + (bl >> 1)) * 2 + (bl & 1)] =
                x[((size_t)(b0 + bl) * T + t) * INP + d];
        }
        __syncthreads();   // x ready; previous h writes visible

        u64 acc[4][4];
        if (act) {
            #pragma unroll
            for (int p = 0; p < 4; p++)
                #pragma unroll
                for (int g = 0; g < 4; g++) {
                    float bv = bias[g * 100 + jj];
                    acc[p][g] = pk2(bv, bv);
                }
            #pragma unroll
            for (int d = 0; d < INP; d++) {
                const float* wr = wihT + d * 400 + jj;
                u64 w0 = pk2(wr[0], wr[0]),   w1 = pk2(wr[100], wr[100]);
                u64 w2 = pk2(wr[200], wr[200]), w3 = pk2(wr[300], wr[300]);
                #pragma unroll
                for (int p = 0; p < 4; p++) {
                    u64 xv = x2u[d * L0_PAIRS + grp * 4 + p];
                    acc[p][0] = ffma2(w0, xv, acc[p][0]);
                    acc[p][1] = ffma2(w1, xv, acc[p][1]);
                    acc[p][2] = ffma2(w2, xv, acc[p][2]);
                    acc[p][3] = ffma2(w3, xv, acc[p][3]);
                }
            }
            #pragma unroll 4
            for (int k = 0; k < H; k++) {
                const float* wr = whh_t + k * 400 + jj;
                u64 w0 = pk2(wr[0], wr[0]),   w1 = pk2(wr[100], wr[100]);
                u64 w2 = pk2(wr[200], wr[200]), w3 = pk2(wr[300], wr[300]);
                const u64* hr = h2u + k * L0_PAD + grp * 4;
                #pragma unroll
                for (int p = 0; p < 4; p++) {
                    u64 hv = hr[p];
                    acc[p][0] = ffma2(w0, hv, acc[p][0]);
                    acc[p][1] = ffma2(w1, hv, acc[p][1]);
                    acc[p][2] = ffma2(w2, hv, acc[p][2]);
                    acc[p][3] = ffma2(w3, hv, acc[p][3]);
                }
            }
        }
        __syncthreads();   // all reads of h done before overwrite

        if (act) {
            #pragma unroll
            for (int p = 0; p < 4; p++) {
                float i0, i1, f0, f1, g0, g1, o0, o1;
                upk2(acc[p][0], i0, i1); upk2(acc[p][1], f0, f1);
                upk2(acc[p][2], g0, g1); upk2(acc[p][3], o0, o1);
                int P = grp * 4 + p;
                float c0 = c_reg[2 * p],     c1 = c_reg[2 * p + 1];
                c0 = sigmoidf_(f0) * c0 + sigmoidf_(i0) * tanhf(g0);
                c1 = sigmoidf_(f1) * c1 + sigmoidf_(i1) * tanhf(g1);
                float hv0 = sigmoidf_(o0) * tanhf(c0);
                float hv1 = sigmoidf_(o1) * tanhf(c1);
                c_reg[2 * p] = c0; c_reg[2 * p + 1] = c1;
                ((float2*)h2f)[jj * L0_PAD + P] = make_float2(hv0, hv1);
                int be = b0 + 2 * P;
                g_h0[((size_t)be * T + t) * 200 + dir * 100 + jj]       = hv0;
                g_h0[((size_t)(be + 1) * T + t) * 200 + dir * 100 + jj] = hv1;
            }
        }
    }
}

// ============================================================================
// Kernel 2: xg1 = h0 @ W_ih_l1f^T + (b_ih+b_hh).  M=131072, K=200, N=400.
// grid (1024, 5), block 256. BM=128, BN=80, BK=8. f32x2-packed (m-pairs).
// ============================================================================
__global__ void __launch_bounds__(256) gemm_xg1_kernel(
    const float* __restrict__ wih,
    const float* __restrict__ bih, const float* __restrict__ bhh)
{
    __shared__ float As[8][132];
    __shared__ float Bs[8][84];
    const int tid = threadIdx.x;
    const int m0 = blockIdx.x * 128;
    const int n0 = blockIdx.y * 80;
    const int tx = tid & 15, ty = tid >> 4;
    const int arow = tid >> 1, aseg = tid & 1;

    u64 acc[4][5];
    #pragma unroll
    for (int i = 0; i < 4; i++)
        #pragma unroll
        for (int n = 0; n < 5; n++) acc[i][n] = pk2(0.f, 0.f);

    for (int k0 = 0; k0 < 200; k0 += 8) {
        float4 av = *(const float4*)(g_h0 + (size_t)(m0 + arow) * 200 + k0 + aseg * 4);
        As[aseg * 4 + 0][arow] = av.x; As[aseg * 4 + 1][arow] = av.y;
        As[aseg * 4 + 2][arow] = av.z; As[aseg * 4 + 3][arow] = av.w;
        if (tid < 160) {
            int n = tid >> 1, seg = tid & 1;
            float4 bv = *(const float4*)(wih + (size_t)(n0 + n) * 200 + k0 + seg * 4);
            Bs[seg * 4 + 0][n] = bv.x; Bs[seg * 4 + 1][n] = bv.y;
            Bs[seg * 4 + 2][n] = bv.z; Bs[seg * 4 + 3][n] = bv.w;
        }
        __syncthreads();
        #pragma unroll
        for (int kk = 0; kk < 8; kk++) {
            u64 a2[4];
            #pragma unroll
            for (int i = 0; i < 4; i++)
                a2[i] = *(const u64*)&As[kk][ty * 8 + 2 * i];
            #pragma unroll
            for (int n = 0; n < 5; n++) {
                float bb = Bs[kk][tx * 5 + n];
                u64 b2 = pk2(bb, bb);
                #pragma unroll
                for (int i = 0; i < 4; i++) acc[i][n] = ffma2(a2[i], b2, acc[i][n]);
            }
        }
        __syncthreads();
    }
    #pragma unroll
    for (int n = 0; n < 5; n++) {
        int gn = n0 + tx * 5 + n;
        float bv = bih[gn] + bhh[gn];
        #pragma unroll
        for (int i = 0; i < 4; i++) {
            float v0, v1; upk2(acc[i][n], v0, v1);
            int m = m0 + ty * 8 + 2 * i;
            g_xg1[(size_t)m * 400 + gn]       = v0 + bv;
            g_xg1[(size_t)(m + 1) * 400 + gn] = v1 + bv;
        }
    }
}

// ============================================================================
// Kernel 3: layer1 forward recurrence; only final h kept.
// grid=128, block=256, 8 batches/CTA (2 f32x2 pairs per thread).
// smem floats: WHH_T 40000 | H2 100*5*2
// ============================================================================
#define L1_NB  8
#define L1_PAD 5
#define L1_SMEMF (40000 + 100*L1_PAD*2)

__global__ void __launch_bounds__(256, 1) lstm_layer1f(const float* __restrict__ whh)
{
    extern __shared__ float sm[];
    float* whh_t = sm;              // [100][400]
    float* h2f   = sm + 40000;      // float2 [100][5]
    const int tid = threadIdx.x;
    const int b0 = blockIdx.x * L1_NB;

    for (int i = tid; i < 40000; i += 256) {
        int g = i / 100, k = i - g * 100;
        whh_t[k * 400 + g] = whh[i];
    }
    for (int i = tid; i < 100 * L1_PAD * 2; i += 256) h2f[i] = 0.f;

    const int  jj  = tid & 127;
    const int  grp = tid >> 7;
    const bool act = (jj < H);
    float c_reg[4] = {0.f, 0.f, 0.f, 0.f};
    const u64* h2u = (const u64*)h2f;

    __syncthreads();

    for (int t = 0; t < T; t++) {
        u64 acc[2][4];
        if (act) {
            #pragma unroll
            for (int p = 0; p < 2; p++) {
                int P = grp * 2 + p;
                const float* xga = g_xg1 + ((size_t)(b0 + 2 * P) * T + t) * 400 + jj;
                const float* xgb = xga + (size_t)T * 400;
                #pragma unroll
                for (int g = 0; g < 4; g++)
                    acc[p][g] = pk2(xga[g * 100], xgb[g * 100]);
            }
            #pragma unroll 4
            for (int k = 0; k < H; k++) {
                const float* wr = whh_t + k * 400 + jj;
                u64 w0 = pk2(wr[0], wr[0]),   w1 = pk2(wr[100], wr[100]);
                u64 w2 = pk2(wr[200], wr[200]), w3 = pk2(wr[300], wr[300]);
                const u64* hr = h2u + k * L1_PAD + grp * 2;
                #pragma unroll
                for (int p = 0; p < 2; p++) {
                    u64 hv = hr[p];
                    acc[p][0] = ffma2(w0, hv, acc[p][0]);
                    acc[p][1] = ffma2(w1, hv, acc[p][1]);
                    acc[p][2] = ffma2(w2, hv, acc[p][2]);
                    acc[p][3] = ffma2(w3, hv, acc[p][3]);
                }
            }
        }
        __syncthreads();
        if (act) {
            #pragma unroll
            for (int p = 0; p < 2; p++) {
                float i0, i1, f0, f1, g0, g1, o0, o1;
                upk2(acc[p][0], i0, i1); upk2(acc[p][1], f0, f1);
                upk2(acc[p][2], g0, g1); upk2(acc[p][3], o0, o1);
                int P = grp * 2 + p;
                float c0 = c_reg[2 * p],     c1 = c_reg[2 * p + 1];
                c0 = sigmoidf_(f0) * c0 + sigmoidf_(i0) * tanhf(g0);
                c1 = sigmoidf_(f1) * c1 + sigmoidf_(i1) * tanhf(g1);
                float hv0 = sigmoidf_(o0) * tanhf(c0);
                float hv1 = sigmoidf_(o1) * tanhf(c1);
                c_reg[2 * p] = c0; c_reg[2 * p + 1] = c1;
                ((float2*)h2f)[jj * L1_PAD + P] = make_float2(hv0, hv1);
                if (t == T - 1) {
                    int be = b0 + 2 * P;
                    g_h1f[(size_t)be * 100 + jj]       = hv0;
                    g_h1f[(size_t)(be + 1) * 100 + jj] = hv1;
                }
            }
        }
        __syncthreads();
    }
}

// ============================================================================
// Kernel 4: layer1 backward = SINGLE step from zero state on h0[:,T-1,:],
// then FC (200->3) + softmax, fused. grid=32 (32 batches each), block=256.
// smem floats: WT 40000 | H0 200*33 | H1B 3200 | BIAS 400 | FCW 600 | FCB 4 | LG 96
// ============================================================================
#define FN_SMEMF (40000 + 200*33 + 3200 + 400 + 600 + 4 + 96)

__global__ void __launch_bounds__(256, 1) lstm_final(
    const float* __restrict__ wih1b,
    const float* __restrict__ bih1b, const float* __restrict__ bhh1b,
    const float* __restrict__ fc_w,  const float* __restrict__ fc_b,
    float* __restrict__ out)
{
    extern __shared__ float sm[];
    float* wT   = sm;                  // [100][400] one k-tile of W_ih_l1b^T
    float* h0s  = sm + 40000;          // [200][33]  h0 at t=T-1
    float* h1bs = sm + 46600;          // [32][100]
    float* bias = sm + 49800;          // [400]
    float* fcw  = sm + 50200;          // [600]
    float* fcb  = sm + 50800;          // [4]
    float* lg   = sm + 50804;          // [96]

    const int tid = threadIdx.x;
    const int b0 = blockIdx.x * 32;

    for (int i = tid; i < 32 * 200; i += 256) {
        int b = i / 200, k = i - b * 200;
        h0s[k * 33 + b] = g_h0[((size_t)(b0 + b) * T + (T - 1)) * 200 + k];
    }
    for (int i = tid; i < 400; i += 256) bias[i] = bih1b[i] + bhh1b[i];
    for (int i = tid; i < 600; i += 256) fcw[i] = fc_w[i];
    if (tid < 3) fcb[tid] = fc_b[tid];

    const int  jj  = tid & 127;
    const int  grp = tid >> 7;
    const bool act = (jj < H);

    float acc[16][4];
    #pragma unroll
    for (int bl = 0; bl < 16; bl++)
        #pragma unroll
        for (int g = 0; g < 4; g++) acc[bl][g] = 0.f;

    for (int kt = 0; kt < 2; kt++) {
        __syncthreads();
        for (int i = tid; i < 40000; i += 256) {
            int g = i / 100, k = i - g * 100;
            wT[k * 400 + g] = wih1b[(size_t)g * 200 + kt * 100 + k];
        }
        __syncthreads();
        if (act) {
            for (int k = 0; k < 100; k++) {
                const float* wr = wT + k * 400 + jj;
                float w0 = wr[0], w1 = wr[100], w2 = wr[200], w3 = wr[300];
                const float* hr = h0s + (kt * 100 + k) * 33 + grp * 16;
                #pragma unroll
                for (int bl = 0; bl < 16; bl++) {
                    float hv = hr[bl];
                    acc[bl][0] += w0 * hv; acc[bl][1] += w1 * hv;
                    acc[bl][2] += w2 * hv; acc[bl][3] += w3 * hv;
                }
            }
        }
    }
    if (act) {
        #pragma unroll
        for (int bl = 0; bl < 16; bl++) {
            int b = grp * 16 + bl;
            float iv = acc[bl][0] + bias[jj];
            float gv = acc[bl][2] + bias[200 + jj];
            float ov = acc[bl][3] + bias[300 + jj];
            // c_prev = 0 -> forget gate contributes nothing
            float c = sigmoidf_(iv) * tanhf(gv);
            h1bs[b * 100 + jj] = sigmoidf_(ov) * tanhf(c);
        }
    }
    __syncthreads();
    if (tid < 96) {
        int b = tid / 3, cls = tid - b * 3;
        float a = fcb[cls];
        const float* h1f = g_h1f + (size_t)(b0 + b) * 100;
        for (int j = 0; j < 100; j++) {
            a += h1f[j]          * fcw[cls * 200 + j];
            a += h1bs[b * 100 + j] * fcw[cls * 200 + 100 + j];
        }
        lg[b * 3 + cls] = a;
    }
    __syncthreads();
    if (tid < 32) {
        int b = tid;
        float l0 = lg[b * 3], l1 = lg[b * 3 + 1], l2 = lg[b * 3 + 2];
        float m = fmaxf(l0, fmaxf(l1, l2));
        float e0 = __expf(l0 - m), e1 = __expf(l1 - m), e2 = __expf(l2 - m);
        float s = e0 + e1 + e2;
        out[(b0 + b) * 3 + 0] = e0 / s;
        out[(b0 + b) * 3 + 1] = e1 / s;
        out[(b0 + b) * 3 + 2] = e2 / s;
    }
}

// ============================================================================
extern "C" void kernel_launch(void* const* d_in, const int* in_sizes, int n_in,
                              void* d_out, int out_size)
{
    (void)in_sizes; (void)n_in; (void)out_size;
    const float* x     = (const float*)d_in[0];
    const float* wih0f = (const float*)d_in[1];
    const float* whh0f = (const float*)d_in[2];
    const float* bih0f = (const float*)d_in[3];
    const float* bhh0f = (const float*)d_in[4];
    const float* wih0b = (const float*)d_in[5];
    const float* whh0b = (const float*)d_in[6];
    const float* bih0b = (const float*)d_in[7];
    const float* bhh0b = (const float*)d_in[8];
    const float* wih1f = (const float*)d_in[9];
    const float* whh1f = (const float*)d_in[10];
    const float* bih1f = (const float*)d_in[11];
    const float* bhh1f = (const float*)d_in[12];
    const float* wih1b = (const float*)d_in[13];
    const float* whh1b = (const float*)d_in[14];  (void)whh1b; // never needed (1-step)
    const float* bih1b = (const float*)d_in[15];
    const float* bhh1b = (const float*)d_in[16];
    const float* fcw   = (const float*)d_in[17];
    const float* fcb   = (const float*)d_in[18];
    float* out = (float*)d_out;

    const int sm0 = L0_SMEMF * 4;
    const int sm1 = L1_SMEMF * 4;
    const int sm2 = FN_SMEMF * 4;
    cudaFuncSetAttribute(lstm_layer0,  cudaFuncAttributeMaxDynamicSharedMemorySize, sm0);
    cudaFuncSetAttribute(lstm_layer1f, cudaFuncAttributeMaxDynamicSharedMemorySize, sm1);
    cudaFuncSetAttribute(lstm_final,   cudaFuncAttributeMaxDynamicSharedMemorySize, sm2);

    lstm_layer0<<<128, 256, sm0>>>(x, wih0f, whh0f, bih0f, bhh0f,
                                      wih0b, whh0b, bih0b, bhh0b);
    gemm_xg1_kernel<<<dim3(1024, 5), 256>>>(wih1f, bih1f, bhh1f);
    lstm_layer1f<<<128, 256, sm1>>>(whh1f);
    lstm_final<<<32, 256, sm2>>>(wih1b, bih1b, bhh1b, fcw, fcb, out);
}

// round 2
// speedup vs baseline: 1.1795x; 1.1795x over previous
#include <cuda_runtime.h>
#include <cstdint>

#define B 1024
#define T 128
#define INP 5
#define H 100
#define G4 400   // 4*H

// ---------------- scratch (device globals; no runtime allocation) ----------
__device__ float g_h0 [B * T * 2 * H];   // [b][t][200]  layer0 output (fwd|bwd)
__device__ float g_xg1[B * T * G4];      // [b*T+t][400] layer1-fwd input gates (+biases)
__device__ float g_h1f[B * H];           // layer1-fwd final hidden

typedef unsigned long long u64;

// ---------------- packed fp32x2 helpers ------------------------------------
__device__ __forceinline__ u64 pk2(float a, float b) {
    u64 r; asm("mov.b64 %0, {%1,%2};" : "=l"(r) : "f"(a), "f"(b)); return r;
}
__device__ __forceinline__ void upk2(u64 v, float& a, float& b) {
    asm("mov.b64 {%0,%1}, %2;" : "=f"(a), "=f"(b) : "l"(v));
}
__device__ __forceinline__ u64 ffma2(u64 a, u64 b, u64 c) {
    asm("fma.rn.f32x2 %0, %1, %2, %0;" : "+l"(c) : "l"(a), "l"(b)); return c;
}

// ---------------- fast activations (ex2.approx + rcp.approx, ~1e-6 err) ----
__device__ __forceinline__ float fsig(float x) {
    float e; asm("ex2.approx.f32 %0, %1;" : "=f"(e) : "f"(x * -1.4426950408889634f));
    float r; asm("rcp.approx.f32 %0, %1;" : "=f"(r) : "f"(e + 1.0f));
    return r;
}
__device__ __forceinline__ float ftanh_(float x) {
    float e; asm("ex2.approx.f32 %0, %1;" : "=f"(e) : "f"(x * -2.885390081777927f));
    float r; asm("rcp.approx.f32 %0, %1;" : "=f"(r) : "f"(e + 1.0f));
    return fmaf(2.0f, r, -1.0f);
}

// ============================================================================
// Kernel 1: layer0, both directions. grid=128 (dir*64+chunk), block=256.
// 16 batch rows/CTA, W_hh^T resident in SMEM, double-buffered h & x,
// ONE __syncthreads per step.
// smem floats: WHH_T 40000 | WIH_T 2000 | BIAS 400 | H2x2 3600 | X2x2 160
// ============================================================================
#define L0_NB    16
#define L0_PAIRS 8
#define L0_PAD   9
#define L0_HBUF  (100*L0_PAD*2)          // 1800 floats per buffer
#define L0_XBUF  (INP*L0_PAIRS*2)        // 80 floats per buffer
#define L0_SMEMF (40000 + 2000 + 400 + 2*L0_HBUF + 2*L0_XBUF)

__global__ void __launch_bounds__(256, 1) lstm_layer0(
    const float* __restrict__ x,
    const float* __restrict__ wih_f, const float* __restrict__ whh_f,
    const float* __restrict__ bih_f, const float* __restrict__ bhh_f,
    const float* __restrict__ wih_b, const float* __restrict__ whh_b,
    const float* __restrict__ bih_b, const float* __restrict__ bhh_b)
{
    extern __shared__ float sm[];
    float* whh_t = sm;                          // [100][400] (k-major)
    float* wihT  = sm + 40000;                  // [5][400]
    float* bias  = sm + 42000;                  // [400]
    float* h2f   = sm + 42400;                  // 2 buffers, float2 [100][9]
    float* x2f   = sm + 42400 + 2*L0_HBUF;      // 2 buffers, float2 [5][8]

    const int tid = threadIdx.x;
    const int dir = blockIdx.x >> 6;
    const int b0  = (blockIdx.x & 63) * L0_NB;
    const float* wih = dir ? wih_b : wih_f;
    const float* whh = dir ? whh_b : whh_f;
    const float* bih = dir ? bih_b : bih_f;
    const float* bhh = dir ? bhh_b : bhh_f;

    for (int i = tid; i < 40000; i += 256) {
        int g = i / 100, k = i - g * 100;
        whh_t[k * 400 + g] = whh[i];
    }
    for (int i = tid; i < 2000; i += 256) {
        int g = i / 5, d = i - g * 5;
        wihT[d * 400 + g] = wih[i];
    }
    for (int i = tid; i < 400; i += 256) bias[i] = bih[i] + bhh[i];
    for (int i = tid; i < L0_HBUF; i += 256) h2f[i] = 0.f;   // buffer 0 only

    // prime x buffer 0 for first step
    {
        int t0 = dir ? (T - 1) : 0;
        if (tid < L0_NB * INP) {
            int bl = tid / INP, d = tid - bl * INP;
            x2f[(d * L0_PAIRS + (bl >> 1)) * 2 + (bl & 1)] =
                x[((size_t)(b0 + bl) * T + t0) * INP + d];
        }
    }

    const int  jj  = tid & 127;
    const int  grp = tid >> 7;
    const bool act = (jj < H);
    float c_reg[8];
    #pragma unroll
    for (int i = 0; i < 8; i++) c_reg[i] = 0.f;

    __syncthreads();

    for (int ts = 0; ts < T; ts++) {
        const int t   = dir ? (T - 1 - ts) : ts;
        const int cur = ts & 1, nxt = cur ^ 1;
        const u64* h2u = (const u64*)(h2f + cur * L0_HBUF);
        const u64* x2u = (const u64*)(x2f + cur * L0_XBUF);

        u64 acc[4][4];
        if (act) {
            #pragma unroll
            for (int g = 0; g < 4; g++) {
                float bv = bias[g * 100 + jj];
                u64 b2 = pk2(bv, bv);
                #pragma unroll
                for (int p = 0; p < 4; p++) acc[p][g] = b2;
            }
            #pragma unroll
            for (int d = 0; d < INP; d++) {
                const float* wr = wihT + d * 400 + jj;
                u64 w0 = pk2(wr[0], wr[0]),     w1 = pk2(wr[100], wr[100]);
                u64 w2 = pk2(wr[200], wr[200]), w3 = pk2(wr[300], wr[300]);
                #pragma unroll
                for (int p = 0; p < 4; p++) {
                    u64 xv = x2u[d * L0_PAIRS + grp * 4 + p];
                    acc[p][0] = ffma2(w0, xv, acc[p][0]);
                    acc[p][1] = ffma2(w1, xv, acc[p][1]);
                    acc[p][2] = ffma2(w2, xv, acc[p][2]);
                    acc[p][3] = ffma2(w3, xv, acc[p][3]);
                }
            }
            #pragma unroll 4
            for (int k = 0; k < H; k++) {
                const float* wr = whh_t + k * 400 + jj;
                u64 w0 = pk2(wr[0], wr[0]),     w1 = pk2(wr[100], wr[100]);
                u64 w2 = pk2(wr[200], wr[200]), w3 = pk2(wr[300], wr[300]);
                const u64* hr = h2u + k * L0_PAD + grp * 4;
                #pragma unroll
                for (int p = 0; p < 4; p++) {
                    u64 hv = hr[p];
                    acc[p][0] = ffma2(w0, hv, acc[p][0]);
                    acc[p][1] = ffma2(w1, hv, acc[p][1]);
                    acc[p][2] = ffma2(w2, hv, acc[p][2]);
                    acc[p][3] = ffma2(w3, hv, acc[p][3]);
                }
            }
        }

        // stage x for next step into the other buffer (no conflict)
        if (ts + 1 < T && tid < L0_NB * INP) {
            int tn = dir ? (T - 2 - ts) : (ts + 1);
            int bl = tid / INP, d = tid - bl * INP;
            x2f[nxt * L0_XBUF + (d * L0_PAIRS + (bl >> 1)) * 2 + (bl & 1)] =
                x[((size_t)(b0 + bl) * T + tn) * INP + d];
        }

        if (act) {
            float2* hw = (float2*)(h2f + nxt * L0_HBUF);
            #pragma unroll
            for (int p = 0; p < 4; p++) {
                float i0, i1, f0, f1, g0, g1, o0, o1;
                upk2(acc[p][0], i0, i1); upk2(acc[p][1], f0, f1);
                upk2(acc[p][2], g0, g1); upk2(acc[p][3], o0, o1);
                int P = grp * 4 + p;
                float c0 = c_reg[2 * p],     c1 = c_reg[2 * p + 1];
                c0 = fsig(f0) * c0 + fsig(i0) * ftanh_(g0);
                c1 = fsig(f1) * c1 + fsig(i1) * ftanh_(g1);
                float hv0 = fsig(o0) * ftanh_(c0);
                float hv1 = fsig(o1) * ftanh_(c1);
                c_reg[2 * p] = c0; c_reg[2 * p + 1] = c1;
                hw[jj * L0_PAD + P] = make_float2(hv0, hv1);
                int be = b0 + 2 * P;
                g_h0[((size_t)be * T + t) * 200 + dir * 100 + jj]       = hv0;
                g_h0[((size_t)(be + 1) * T + t) * 200 + dir * 100 + jj] = hv1;
            }
        }
        __syncthreads();   // single barrier per step
    }
}

// ============================================================================
// Kernel 2: xg1 = h0 @ W_ih_l1f^T + (b_ih+b_hh).  M=131072, K=200, N=400.
// grid (1024, 5), block 256. BM=128, BN=80, BK=8. Double-buffered SMEM,
// one sync per k-tile.
// ============================================================================
__global__ void __launch_bounds__(256) gemm_xg1_kernel(
    const float* __restrict__ wih,
    const float* __restrict__ bih, const float* __restrict__ bhh)
{
    __shared__ float As[2][8][132];
    __shared__ float Bs[2][8][84];
    const int tid = threadIdx.x;
    const int m0 = blockIdx.x * 128;
    const int n0 = blockIdx.y * 80;
    const int tx = tid & 15, ty = tid >> 4;
    const int arow = tid >> 1, aseg = tid & 1;
    const int brow = tid >> 1, bseg = tid & 1;

    u64 acc[4][5];
    #pragma unroll
    for (int i = 0; i < 4; i++)
        #pragma unroll
        for (int n = 0; n < 5; n++) acc[i][n] = pk2(0.f, 0.f);

    // preload tile 0
    float4 av = *(const float4*)(g_h0 + (size_t)(m0 + arow) * 200 + aseg * 4);
    float4 bv = make_float4(0.f, 0.f, 0.f, 0.f);
    if (tid < 160)
        bv = *(const float4*)(wih + (size_t)(n0 + brow) * 200 + bseg * 4);
    As[0][aseg * 4 + 0][arow] = av.x; As[0][aseg * 4 + 1][arow] = av.y;
    As[0][aseg * 4 + 2][arow] = av.z; As[0][aseg * 4 + 3][arow] = av.w;
    if (tid < 160) {
        Bs[0][bseg * 4 + 0][brow] = bv.x; Bs[0][bseg * 4 + 1][brow] = bv.y;
        Bs[0][bseg * 4 + 2][brow] = bv.z; Bs[0][bseg * 4 + 3][brow] = bv.w;
    }
    __syncthreads();

    for (int kt = 0; kt < 25; kt++) {
        const int cur = kt & 1, nx = cur ^ 1;
        if (kt < 24) {
            int k0 = (kt + 1) * 8;
            av = *(const float4*)(g_h0 + (size_t)(m0 + arow) * 200 + k0 + aseg * 4);
            if (tid < 160)
                bv = *(const float4*)(wih + (size_t)(n0 + brow) * 200 + k0 + bseg * 4);
        }
        #pragma unroll
        for (int kk = 0; kk < 8; kk++) {
            u64 a2[4];
            #pragma unroll
            for (int i = 0; i < 4; i++)
                a2[i] = *(const u64*)&As[cur][kk][ty * 8 + 2 * i];
            #pragma unroll
            for (int n = 0; n < 5; n++) {
                float bb = Bs[cur][kk][tx * 5 + n];
                u64 b2 = pk2(bb, bb);
                #pragma unroll
                for (int i = 0; i < 4; i++) acc[i][n] = ffma2(a2[i], b2, acc[i][n]);
            }
        }
        if (kt < 24) {
            As[nx][aseg * 4 + 0][arow] = av.x; As[nx][aseg * 4 + 1][arow] = av.y;
            As[nx][aseg * 4 + 2][arow] = av.z; As[nx][aseg * 4 + 3][arow] = av.w;
            if (tid < 160) {
                Bs[nx][bseg * 4 + 0][brow] = bv.x; Bs[nx][bseg * 4 + 1][brow] = bv.y;
                Bs[nx][bseg * 4 + 2][brow] = bv.z; Bs[nx][bseg * 4 + 3][brow] = bv.w;
            }
            __syncthreads();
        }
    }
    #pragma unroll
    for (int n = 0; n < 5; n++) {
        int gn = n0 + tx * 5 + n;
        float bvv = bih[gn] + bhh[gn];
        #pragma unroll
        for (int i = 0; i < 4; i++) {
            float v0, v1; upk2(acc[i][n], v0, v1);
            int m = m0 + ty * 8 + 2 * i;
            g_xg1[(size_t)m * 400 + gn]       = v0 + bvv;
            g_xg1[(size_t)(m + 1) * 400 + gn] = v1 + bvv;
        }
    }
}

// ============================================================================
// Kernel 3: layer1 forward recurrence; only final h kept.
// grid=128, block=256, 8 batches/CTA. Double-buffered h (1 sync/step),
// xg for step t+1 prefetched into registers during step t's k-loop.
// smem floats: WHH_T 40000 | H2 x2 (100*5*2 each)
// ============================================================================
#define L1_NB   8
#define L1_PAD  5
#define L1_HBUF (100*L1_PAD*2)
#define L1_SMEMF (40000 + 2*L1_HBUF)

__global__ void __launch_bounds__(256, 1) lstm_layer1f(const float* __restrict__ whh)
{
    extern __shared__ float sm[];
    float* whh_t = sm;              // [100][400]
    float* h2f   = sm + 40000;      // 2 buffers float2 [100][5]
    const int tid = threadIdx.x;
    const int b0 = blockIdx.x * L1_NB;

    for (int i = tid; i < 40000; i += 256) {
        int g = i / 100, k = i - g * 100;
        whh_t[k * 400 + g] = whh[i];
    }
    for (int i = tid; i < L1_HBUF; i += 256) h2f[i] = 0.f;   // buffer 0

    const int  jj  = tid & 127;
    const int  grp = tid >> 7;
    const bool act = (jj < H);
    float c_reg[4] = {0.f, 0.f, 0.f, 0.f};

    float xr[2][4][2];
    if (act) {
        #pragma unroll
        for (int p = 0; p < 2; p++) {
            int P = grp * 2 + p;
            const float* xga = g_xg1 + ((size_t)(b0 + 2 * P) * T + 0) * 400 + jj;
            const float* xgb = xga + (size_t)T * 400;
            #pragma unroll
            for (int g = 0; g < 4; g++) { xr[p][g][0] = xga[g * 100]; xr[p][g][1] = xgb[g * 100]; }
        }
    }

    __syncthreads();

    for (int t = 0; t < T; t++) {
        const int cur = t & 1, nxt = cur ^ 1;
        const u64* h2u = (const u64*)(h2f + cur * L1_HBUF);

        u64 acc[2][4];
        if (act) {
            #pragma unroll
            for (int p = 0; p < 2; p++)
                #pragma unroll
                for (int g = 0; g < 4; g++)
                    acc[p][g] = pk2(xr[p][g][0], xr[p][g][1]);

            if (t + 1 < T) {   // prefetch next step's xg; lands during k-loop
                #pragma unroll
                for (int p = 0; p < 2; p++) {
                    int P = grp * 2 + p;
                    const float* xga = g_xg1 + ((size_t)(b0 + 2 * P) * T + (t + 1)) * 400 + jj;
                    const float* xgb = xga + (size_t)T * 400;
                    #pragma unroll
                    for (int g = 0; g < 4; g++) { xr[p][g][0] = xga[g * 100]; xr[p][g][1] = xgb[g * 100]; }
                }
            }

            #pragma unroll 4
            for (int k = 0; k < H; k++) {
                const float* wr = whh_t + k * 400 + jj;
                u64 w0 = pk2(wr[0], wr[0]),     w1 = pk2(wr[100], wr[100]);
                u64 w2 = pk2(wr[200], wr[200]), w3 = pk2(wr[300], wr[300]);
                const u64* hr = h2u + k * L1_PAD + grp * 2;
                #pragma unroll
                for (int p = 0; p < 2; p++) {
                    u64 hv = hr[p];
                    acc[p][0] = ffma2(w0, hv, acc[p][0]);
                    acc[p][1] = ffma2(w1, hv, acc[p][1]);
                    acc[p][2] = ffma2(w2, hv, acc[p][2]);
                    acc[p][3] = ffma2(w3, hv, acc[p][3]);
                }
            }

            float2* hw = (float2*)(h2f + nxt * L1_HBUF);
            #pragma unroll
            for (int p = 0; p < 2; p++) {
                float i0, i1, f0, f1, g0, g1, o0, o1;
                upk2(acc[p][0], i0, i1); upk2(acc[p][1], f0, f1);
                upk2(acc[p][2], g0, g1); upk2(acc[p][3], o0, o1);
                int P = grp * 2 + p;
                float c0 = c_reg[2 * p],     c1 = c_reg[2 * p + 1];
                c0 = fsig(f0) * c0 + fsig(i0) * ftanh_(g0);
                c1 = fsig(f1) * c1 + fsig(i1) * ftanh_(g1);
                float hv0 = fsig(o0) * ftanh_(c0);
                float hv1 = fsig(o1) * ftanh_(c1);
                c_reg[2 * p] = c0; c_reg[2 * p + 1] = c1;
                hw[jj * L1_PAD + P] = make_float2(hv0, hv1);
                if (t == T - 1) {
                    int be = b0 + 2 * P;
                    g_h1f[(size_t)be * 100 + jj]       = hv0;
                    g_h1f[(size_t)(be + 1) * 100 + jj] = hv1;
                }
            }
        }
        __syncthreads();
    }
}

// ============================================================================
// Kernel 4: layer1 backward = SINGLE step from zero state on h0[:,T-1,:],
// then FC (200->3) + softmax. grid=128 (8 batches each), block=256.
// smem floats: WT 40000 | H0 200*9 | H1B 800 | BIAS 400 | FCW 600 | FCB 4 | LG 24
// ============================================================================
#define FN_SMEMF (40000 + 200*9 + 800 + 400 + 600 + 4 + 24)

__global__ void __launch_bounds__(256, 1) lstm_final(
    const float* __restrict__ wih1b,
    const float* __restrict__ bih1b, const float* __restrict__ bhh1b,
    const float* __restrict__ fc_w,  const float* __restrict__ fc_b,
    float* __restrict__ out)
{
    extern __shared__ float sm[];
    float* wT   = sm;                  // [100][400] one k-tile of W_ih_l1b^T
    float* h0s  = sm + 40000;          // [200][9]  h0 at t=T-1
    float* h1bs = sm + 41800;          // [8][100]
    float* bias = sm + 42600;          // [400]
    float* fcw  = sm + 43000;          // [600]
    float* fcb  = sm + 43600;          // [4]
    float* lg   = sm + 43604;          // [24]

    const int tid = threadIdx.x;
    const int b0 = blockIdx.x * 8;

    for (int i = tid; i < 8 * 200; i += 256) {
        int b = i / 200, k = i - b * 200;
        h0s[k * 9 + b] = g_h0[((size_t)(b0 + b) * T + (T - 1)) * 200 + k];
    }
    for (int i = tid; i < 400; i += 256) bias[i] = bih1b[i] + bhh1b[i];
    for (int i = tid; i < 600; i += 256) fcw[i] = fc_w[i];
    if (tid < 3) fcb[tid] = fc_b[tid];

    const int  jj  = tid & 127;
    const int  grp = tid >> 7;
    const bool act = (jj < H);

    float acc[4][4];
    #pragma unroll
    for (int bl = 0; bl < 4; bl++)
        #pragma unroll
        for (int g = 0; g < 4; g++) acc[bl][g] = 0.f;

    for (int kt = 0; kt < 2; kt++) {
        __syncthreads();
        for (int i = tid; i < 40000; i += 256) {
            int g = i / 100, k = i - g * 100;
            wT[k * 400 + g] = wih1b[(size_t)g * 200 + kt * 100 + k];
        }
        __syncthreads();
        if (act) {
            #pragma unroll 2
            for (int k = 0; k < 100; k++) {
                const float* wr = wT + k * 400 + jj;
                float w0 = wr[0], w1 = wr[100], w2 = wr[200], w3 = wr[300];
                const float* hr = h0s + (kt * 100 + k) * 9 + grp * 4;
                #pragma unroll
                for (int bl = 0; bl < 4; bl++) {
                    float hv = hr[bl];
                    acc[bl][0] += w0 * hv; acc[bl][1] += w1 * hv;
                    acc[bl][2] += w2 * hv; acc[bl][3] += w3 * hv;
                }
            }
        }
    }
    if (act) {
        #pragma unroll
        for (int bl = 0; bl < 4; bl++) {
            int b = grp * 4 + bl;
            float iv = acc[bl][0] + bias[jj];
            float gv = acc[bl][2] + bias[200 + jj];
            float ov = acc[bl][3] + bias[300 + jj];
            float c = fsig(iv) * ftanh_(gv);     // c_prev = 0
            h1bs[b * 100 + jj] = fsig(ov) * ftanh_(c);
        }
    }
    __syncthreads();
    if (tid < 24) {
        int b = tid / 3, cls = tid - b * 3;
        float a = fcb[cls];
        const float* h1f = g_h1f + (size_t)(b0 + b) * 100;
        #pragma unroll 4
        for (int j = 0; j < 100; j++) {
            a += h1f[j]            * fcw[cls * 200 + j];
            a += h1bs[b * 100 + j] * fcw[cls * 200 + 100 + j];
        }
        lg[b * 3 + cls] = a;
    }
    __syncthreads();
    if (tid < 8) {
        int b = tid;
        float l0 = lg[b * 3], l1 = lg[b * 3 + 1], l2 = lg[b * 3 + 2];
        float m = fmaxf(l0, fmaxf(l1, l2));
        float e0 = __expf(l0 - m), e1 = __expf(l1 - m), e2 = __expf(l2 - m);
        float s = 1.0f / (e0 + e1 + e2);
        out[(b0 + b) * 3 + 0] = e0 * s;
        out[(b0 + b) * 3 + 1] = e1 * s;
        out[(b0 + b) * 3 + 2] = e2 * s;
    }
}

// ============================================================================
extern "C" void kernel_launch(void* const* d_in, const int* in_sizes, int n_in,
                              void* d_out, int out_size)
{
    (void)in_sizes; (void)n_in; (void)out_size;
    const float* x     = (const float*)d_in[0];
    const float* wih0f = (const float*)d_in[1];
    const float* whh0f = (const float*)d_in[2];
    const float* bih0f = (const float*)d_in[3];
    const float* bhh0f = (const float*)d_in[4];
    const float* wih0b = (const float*)d_in[5];
    const float* whh0b = (const float*)d_in[6];
    const float* bih0b = (const float*)d_in[7];
    const float* bhh0b = (const float*)d_in[8];
    const float* wih1f = (const float*)d_in[9];
    const float* whh1f = (const float*)d_in[10];
    const float* bih1f = (const float*)d_in[11];
    const float* bhh1f = (const float*)d_in[12];
    const float* wih1b = (const float*)d_in[13];
    const float* bih1b = (const float*)d_in[15];
    const float* bhh1b = (const float*)d_in[16];
    const float* fcw   = (const float*)d_in[17];
    const float* fcb   = (const float*)d_in[18];
    float* out = (float*)d_out;

    const int sm0 = L0_SMEMF * 4;
    const int sm1 = L1_SMEMF * 4;
    const int sm2 = FN_SMEMF * 4;
    cudaFuncSetAttribute(lstm_layer0,  cudaFuncAttributeMaxDynamicSharedMemorySize, sm0);
    cudaFuncSetAttribute(lstm_layer1f, cudaFuncAttributeMaxDynamicSharedMemorySize, sm1);
    cudaFuncSetAttribute(lstm_final,   cudaFuncAttributeMaxDynamicSharedMemorySize, sm2);

    lstm_layer0<<<128, 256, sm0>>>(x, wih0f, whh0f, bih0f, bhh0f,
                                      wih0b, whh0b, bih0b, bhh0b);
    gemm_xg1_kernel<<<dim3(1024, 5), 256>>>(wih1f, bih1f, bhh1f);
    lstm_layer1f<<<128, 256, sm1>>>(whh1f);
    lstm_final<<<128, 256, sm2>>>(wih1b, bih1b, bhh1b, fcw, fcb, out);
}

// round 3
// speedup vs baseline: 1.1803x; 1.0007x over previous
#include <cuda_runtime.h>
#include <cstdint>

#define B 1024
#define T 128
#define INP 5
#define H 100
#define G4 400   // 4*H

// ---------------- scratch (device globals; no runtime allocation) ----------
__device__ float g_h0 [B * T * 2 * H];   // [b][t][200]  layer0 output (fwd|bwd)
__device__ float g_xg1[B * T * G4];      // [b*T+t][400] layer1-fwd input gates (+biases)
__device__ float g_h1f[B * H];           // layer1-fwd final hidden

typedef unsigned long long u64;

// ---------------- packed fp32x2 helpers ------------------------------------
__device__ __forceinline__ u64 pk2(float a, float b) {
    u64 r; asm("mov.b64 %0, {%1,%2};" : "=l"(r) : "f"(a), "f"(b)); return r;
}
__device__ __forceinline__ void upk2(u64 v, float& a, float& b) {
    asm("mov.b64 {%0,%1}, %2;" : "=f"(a), "=f"(b) : "l"(v));
}
__device__ __forceinline__ u64 ffma2(u64 a, u64 b, u64 c) {
    asm("fma.rn.f32x2 %0, %1, %2, %0;" : "+l"(c) : "l"(a), "l"(b)); return c;
}

// ---------------- fast activations (ex2.approx + rcp.approx, ~1e-6 err) ----
__device__ __forceinline__ float fsig(float x) {
    float e; asm("ex2.approx.f32 %0, %1;" : "=f"(e) : "f"(x * -1.4426950408889634f));
    float r; asm("rcp.approx.f32 %0, %1;" : "=f"(r) : "f"(e + 1.0f));
    return r;
}
__device__ __forceinline__ float ftanh_(float x) {
    float e; asm("ex2.approx.f32 %0, %1;" : "=f"(e) : "f"(x * -2.885390081777927f));
    float r; asm("rcp.approx.f32 %0, %1;" : "=f"(r) : "f"(e + 1.0f));
    return fmaf(2.0f, r, -1.0f);
}

// ============================================================================
// Kernel 1: layer0, both directions. grid=128 (dir*64+chunk), block=256.
// 16 batch rows/CTA, W_hh^T resident in SMEM, double-buffered h & x,
// ONE __syncthreads per step.
// smem floats: WHH_T 40000 | WIH_T 2000 | BIAS 400 | H2x2 3600 | X2x2 160
// ============================================================================
#define L0_NB    16
#define L0_PAIRS 8
#define L0_PAD   9
#define L0_HBUF  (100*L0_PAD*2)          // 1800 floats per buffer
#define L0_XBUF  (INP*L0_PAIRS*2)        // 80 floats per buffer
#define L0_SMEMF (40000 + 2000 + 400 + 2*L0_HBUF + 2*L0_XBUF)

__global__ void __launch_bounds__(256, 1) lstm_layer0(
    const float* __restrict__ x,
    const float* __restrict__ wih_f, const float* __restrict__ whh_f,
    const float* __restrict__ bih_f, const float* __restrict__ bhh_f,
    const float* __restrict__ wih_b, const float* __restrict__ whh_b,
    const float* __restrict__ bih_b, const float* __restrict__ bhh_b)
{
    extern __shared__ float sm[];
    float* whh_t = sm;                          // [100][400] (k-major)
    float* wihT  = sm + 40000;                  // [5][400]
    float* bias  = sm + 42000;                  // [400]
    float* h2f   = sm + 42400;                  // 2 buffers, float2 [100][9]
    float* x2f   = sm + 42400 + 2*L0_HBUF;      // 2 buffers, float2 [5][8]

    const int tid = threadIdx.x;
    const int dir = blockIdx.x >> 6;
    const int b0  = (blockIdx.x & 63) * L0_NB;
    const float* wih = dir ? wih_b : wih_f;
    const float* whh = dir ? whh_b : whh_f;
    const float* bih = dir ? bih_b : bih_f;
    const float* bhh = dir ? bhh_b : bhh_f;

    for (int i = tid; i < 40000; i += 256) {
        int g = i / 100, k = i - g * 100;
        whh_t[k * 400 + g] = whh[i];
    }
    for (int i = tid; i < 2000; i += 256) {
        int g = i / 5, d = i - g * 5;
        wihT[d * 400 + g] = wih[i];
    }
    for (int i = tid; i < 400; i += 256) bias[i] = bih[i] + bhh[i];
    for (int i = tid; i < L0_HBUF; i += 256) h2f[i] = 0.f;   // buffer 0 only

    // prime x buffer 0 for first step
    {
        int t0 = dir ? (T - 1) : 0;
        if (tid < L0_NB * INP) {
            int bl = tid / INP, d = tid - bl * INP;
            x2f[(d * L0_PAIRS + (bl >> 1)) * 2 + (bl & 1)] =
                x[((size_t)(b0 + bl) * T + t0) * INP + d];
        }
    }

    const int  jj  = tid & 127;
    const int  grp = tid >> 7;
    const bool act = (jj < H);
    float c_reg[8];
    #pragma unroll
    for (int i = 0; i < 8; i++) c_reg[i] = 0.f;

    __syncthreads();

    for (int ts = 0; ts < T; ts++) {
        const int t   = dir ? (T - 1 - ts) : ts;
        const int cur = ts & 1, nxt = cur ^ 1;
        const u64* h2u = (const u64*)(h2f + cur * L0_HBUF);
        const u64* x2u = (const u64*)(x2f + cur * L0_XBUF);

        u64 acc[4][4];
        if (act) {
            #pragma unroll
            for (int g = 0; g < 4; g++) {
                float bv = bias[g * 100 + jj];
                u64 b2 = pk2(bv, bv);
                #pragma unroll
                for (int p = 0; p < 4; p++) acc[p][g] = b2;
            }
            #pragma unroll
            for (int d = 0; d < INP; d++) {
                const float* wr = wihT + d * 400 + jj;
                u64 w0 = pk2(wr[0], wr[0]),     w1 = pk2(wr[100], wr[100]);
                u64 w2 = pk2(wr[200], wr[200]), w3 = pk2(wr[300], wr[300]);
                #pragma unroll
                for (int p = 0; p < 4; p++) {
                    u64 xv = x2u[d * L0_PAIRS + grp * 4 + p];
                    acc[p][0] = ffma2(w0, xv, acc[p][0]);
                    acc[p][1] = ffma2(w1, xv, acc[p][1]);
                    acc[p][2] = ffma2(w2, xv, acc[p][2]);
                    acc[p][3] = ffma2(w3, xv, acc[p][3]);
                }
            }
            #pragma unroll 4
            for (int k = 0; k < H; k++) {
                const float* wr = whh_t + k * 400 + jj;
                u64 w0 = pk2(wr[0], wr[0]),     w1 = pk2(wr[100], wr[100]);
                u64 w2 = pk2(wr[200], wr[200]), w3 = pk2(wr[300], wr[300]);
                const u64* hr = h2u + k * L0_PAD + grp * 4;
                #pragma unroll
                for (int p = 0; p < 4; p++) {
                    u64 hv = hr[p];
                    acc[p][0] = ffma2(w0, hv, acc[p][0]);
                    acc[p][1] = ffma2(w1, hv, acc[p][1]);
                    acc[p][2] = ffma2(w2, hv, acc[p][2]);
                    acc[p][3] = ffma2(w3, hv, acc[p][3]);
                }
            }
        }

        // stage x for next step into the other buffer (no conflict)
        if (ts + 1 < T && tid < L0_NB * INP) {
            int tn = dir ? (T - 2 - ts) : (ts + 1);
            int bl = tid / INP, d = tid - bl * INP;
            x2f[nxt * L0_XBUF + (d * L0_PAIRS + (bl >> 1)) * 2 + (bl & 1)] =
                x[((size_t)(b0 + bl) * T + tn) * INP + d];
        }

        if (act) {
            float2* hw = (float2*)(h2f + nxt * L0_HBUF);
            #pragma unroll
            for (int p = 0; p < 4; p++) {
                float i0, i1, f0, f1, g0, g1, o0, o1;
                upk2(acc[p][0], i0, i1); upk2(acc[p][1], f0, f1);
                upk2(acc[p][2], g0, g1); upk2(acc[p][3], o0, o1);
                int P = grp * 4 + p;
                float c0 = c_reg[2 * p],     c1 = c_reg[2 * p + 1];
                c0 = fsig(f0) * c0 + fsig(i0) * ftanh_(g0);
                c1 = fsig(f1) * c1 + fsig(i1) * ftanh_(g1);
                float hv0 = fsig(o0) * ftanh_(c0);
                float hv1 = fsig(o1) * ftanh_(c1);
                c_reg[2 * p] = c0; c_reg[2 * p + 1] = c1;
                hw[jj * L0_PAD + P] = make_float2(hv0, hv1);
                int be = b0 + 2 * P;
                g_h0[((size_t)be * T + t) * 200 + dir * 100 + jj]       = hv0;
                g_h0[((size_t)(be + 1) * T + t) * 200 + dir * 100 + jj] = hv1;
            }
        }
        __syncthreads();   // single barrier per step
    }
}

// ============================================================================
// Kernel 2: xg1 = h0 @ W_ih_l1f^T + (b_ih+b_hh).  M=131072, K=200, N=400.
// grid (1024, 5), block 256. BM=128, BN=80, BK=8. Double-buffered SMEM,
// one sync per k-tile.
// ============================================================================
__global__ void __launch_bounds__(256) gemm_xg1_kernel(
    const float* __restrict__ wih,
    const float* __restrict__ bih, const float* __restrict__ bhh)
{
    __shared__ float As[2][8][132];
    __shared__ float Bs[2][8][84];
    const int tid = threadIdx.x;
    const int m0 = blockIdx.x * 128;
    const int n0 = blockIdx.y * 80;
    const int tx = tid & 15, ty = tid >> 4;
    const int arow = tid >> 1, aseg = tid & 1;
    const int brow = tid >> 1, bseg = tid & 1;

    u64 acc[4][5];
    #pragma unroll
    for (int i = 0; i < 4; i++)
        #pragma unroll
        for (int n = 0; n < 5; n++) acc[i][n] = pk2(0.f, 0.f);

    // preload tile 0
    float4 av = *(const float4*)(g_h0 + (size_t)(m0 + arow) * 200 + aseg * 4);
    float4 bv = make_float4(0.f, 0.f, 0.f, 0.f);
    if (tid < 160)
        bv = *(const float4*)(wih + (size_t)(n0 + brow) * 200 + bseg * 4);
    As[0][aseg * 4 + 0][arow] = av.x; As[0][aseg * 4 + 1][arow] = av.y;
    As[0][aseg * 4 + 2][arow] = av.z; As[0][aseg * 4 + 3][arow] = av.w;
    if (tid < 160) {
        Bs[0][bseg * 4 + 0][brow] = bv.x; Bs[0][bseg * 4 + 1][brow] = bv.y;
        Bs[0][bseg * 4 + 2][brow] = bv.z; Bs[0][bseg * 4 + 3][brow] = bv.w;
    }
    __syncthreads();

    for (int kt = 0; kt < 25; kt++) {
        const int cur = kt & 1, nx = cur ^ 1;
        if (kt < 24) {
            int k0 = (kt + 1) * 8;
            av = *(const float4*)(g_h0 + (size_t)(m0 + arow) * 200 + k0 + aseg * 4);
            if (tid < 160)
                bv = *(const float4*)(wih + (size_t)(n0 + brow) * 200 + k0 + bseg * 4);
        }
        #pragma unroll
        for (int kk = 0; kk < 8; kk++) {
            u64 a2[4];
            #pragma unroll
            for (int i = 0; i < 4; i++)
                a2[i] = *(const u64*)&As[cur][kk][ty * 8 + 2 * i];
            #pragma unroll
            for (int n = 0; n < 5; n++) {
                float bb = Bs[cur][kk][tx * 5 + n];
                u64 b2 = pk2(bb, bb);
                #pragma unroll
                for (int i = 0; i < 4; i++) acc[i][n] = ffma2(a2[i], b2, acc[i][n]);
            }
        }
        if (kt < 24) {
            As[nx][aseg * 4 + 0][arow] = av.x; As[nx][aseg * 4 + 1][arow] = av.y;
            As[nx][aseg * 4 + 2][arow] = av.z; As[nx][aseg * 4 + 3][arow] = av.w;
            if (tid < 160) {
                Bs[nx][bseg * 4 + 0][brow] = bv.x; Bs[nx][bseg * 4 + 1][brow] = bv.y;
                Bs[nx][bseg * 4 + 2][brow] = bv.z; Bs[nx][bseg * 4 + 3][brow] = bv.w;
            }
            __syncthreads();
        }
    }
    #pragma unroll
    for (int n = 0; n < 5; n++) {
        int gn = n0 + tx * 5 + n;
        float bvv = bih[gn] + bhh[gn];
        #pragma unroll
        for (int i = 0; i < 4; i++) {
            float v0, v1; upk2(acc[i][n], v0, v1);
            int m = m0 + ty * 8 + 2 * i;
            g_xg1[(size_t)m * 400 + gn]       = v0 + bvv;
            g_xg1[(size_t)(m + 1) * 400 + gn] = v1 + bvv;
        }
    }
}

// ============================================================================
// Kernel 3: layer1 forward recurrence; only final h kept.
// grid=128, block=256, 8 batches/CTA. Double-buffered h (1 sync/step),
// xg for step t+1 prefetched into registers during step t's k-loop.
// smem floats: WHH_T 40000 | H2 x2 (100*5*2 each)
// ============================================================================
#define L1_NB   8
#define L1_PAD  5
#define L1_HBUF (100*L1_PAD*2)
#define L1_SMEMF (40000 + 2*L1_HBUF)

__global__ void __launch_bounds__(256, 1) lstm_layer1f(const float* __restrict__ whh)
{
    extern __shared__ float sm[];
    float* whh_t = sm;              // [100][400]
    float* h2f   = sm + 40000;      // 2 buffers float2 [100][5]
    const int tid = threadIdx.x;
    const int b0 = blockIdx.x * L1_NB;

    for (int i = tid; i < 40000; i += 256) {
        int g = i / 100, k = i - g * 100;
        whh_t[k * 400 + g] = whh[i];
    }
    for (int i = tid; i < L1_HBUF; i += 256) h2f[i] = 0.f;   // buffer 0

    const int  jj  = tid & 127;
    const int  grp = tid >> 7;
    const bool act = (jj < H);
    float c_reg[4] = {0.f, 0.f, 0.f, 0.f};

    float xr[2][4][2];
    if (act) {
        #pragma unroll
        for (int p = 0; p < 2; p++) {
            int P = grp * 2 + p;
            const float* xga = g_xg1 + ((size_t)(b0 + 2 * P) * T + 0) * 400 + jj;
            const float* xgb = xga + (size_t)T * 400;
            #pragma unroll
            for (int g = 0; g < 4; g++) { xr[p][g][0] = xga[g * 100]; xr[p][g][1] = xgb[g * 100]; }
        }
    }

    __syncthreads();

    for (int t = 0; t < T; t++) {
        const int cur = t & 1, nxt = cur ^ 1;
        const u64* h2u = (const u64*)(h2f + cur * L1_HBUF);

        u64 acc[2][4];
        if (act) {
            #pragma unroll
            for (int p = 0; p < 2; p++)
                #pragma unroll
                for (int g = 0; g < 4; g++)
                    acc[p][g] = pk2(xr[p][g][0], xr[p][g][1]);

            if (t + 1 < T) {   // prefetch next step's xg; lands during k-loop
                #pragma unroll
                for (int p = 0; p < 2; p++) {
                    int P = grp * 2 + p;
                    const float* xga = g_xg1 + ((size_t)(b0 + 2 * P) * T + (t + 1)) * 400 + jj;
                    const float* xgb = xga + (size_t)T * 400;
                    #pragma unroll
                    for (int g = 0; g < 4; g++) { xr[p][g][0] = xga[g * 100]; xr[p][g][1] = xgb[g * 100]; }
                }
            }

            #pragma unroll 4
            for (int k = 0; k < H; k++) {
                const float* wr = whh_t + k * 400 + jj;
                u64 w0 = pk2(wr[0], wr[0]),     w1 = pk2(wr[100], wr[100]);
                u64 w2 = pk2(wr[200], wr[200]), w3 = pk2(wr[300], wr[300]);
                const u64* hr = h2u + k * L1_PAD + grp * 2;
                #pragma unroll
                for (int p = 0; p < 2; p++) {
                    u64 hv = hr[p];
                    acc[p][0] = ffma2(w0, hv, acc[p][0]);
                    acc[p][1] = ffma2(w1, hv, acc[p][1]);
                    acc[p][2] = ffma2(w2, hv, acc[p][2]);
                    acc[p][3] = ffma2(w3, hv, acc[p][3]);
                }
            }

            float2* hw = (float2*)(h2f + nxt * L1_HBUF);
            #pragma unroll
            for (int p = 0; p < 2; p++) {
                float i0, i1, f0, f1, g0, g1, o0, o1;
                upk2(acc[p][0], i0, i1); upk2(acc[p][1], f0, f1);
                upk2(acc[p][2], g0, g1); upk2(acc[p][3], o0, o1);
                int P = grp * 2 + p;
                float c0 = c_reg[2 * p],     c1 = c_reg[2 * p + 1];
                c0 = fsig(f0) * c0 + fsig(i0) * ftanh_(g0);
                c1 = fsig(f1) * c1 + fsig(i1) * ftanh_(g1);
                float hv0 = fsig(o0) * ftanh_(c0);
                float hv1 = fsig(o1) * ftanh_(c1);
                c_reg[2 * p] = c0; c_reg[2 * p + 1] = c1;
                hw[jj * L1_PAD + P] = make_float2(hv0, hv1);
                if (t == T - 1) {
                    int be = b0 + 2 * P;
                    g_h1f[(size_t)be * 100 + jj]       = hv0;
                    g_h1f[(size_t)(be + 1) * 100 + jj] = hv1;
                }
            }
        }
        __syncthreads();
    }
}

// ============================================================================
// Kernel 4: layer1 backward = SINGLE step from zero state on h0[:,T-1,:],
// then FC (200->3) + softmax. grid=128 (8 batches each), block=256.
// smem floats: WT 40000 | H0 200*9 | H1B 800 | BIAS 400 | FCW 600 | FCB 4 | LG 24
// ============================================================================
#define FN_SMEMF (40000 + 200*9 + 800 + 400 + 600 + 4 + 24)

__global__ void __launch_bounds__(256, 1) lstm_final(
    const float* __restrict__ wih1b,
    const float* __restrict__ bih1b, const float* __restrict__ bhh1b,
    const float* __restrict__ fc_w,  const float* __restrict__ fc_b,
    float* __restrict__ out)
{
    extern __shared__ float sm[];
    float* wT   = sm;                  // [100][400] one k-tile of W_ih_l1b^T
    float* h0s  = sm + 40000;          // [200][9]  h0 at t=T-1
    float* h1bs = sm + 41800;          // [8][100]
    float* bias = sm + 42600;          // [400]
    float* fcw  = sm + 43000;          // [600]
    float* fcb  = sm + 43600;          // [4]
    float* lg   = sm + 43604;          // [24]

    const int tid = threadIdx.x;
    const int b0 = blockIdx.x * 8;

    for (int i = tid; i < 8 * 200; i += 256) {
        int b = i / 200, k = i - b * 200;
        h0s[k * 9 + b] = g_h0[((size_t)(b0 + b) * T + (T - 1)) * 200 + k];
    }
    for (int i = tid; i < 400; i += 256) bias[i] = bih1b[i] + bhh1b[i];
    for (int i = tid; i < 600; i += 256) fcw[i] = fc_w[i];
    if (tid < 3) fcb[tid] = fc_b[tid];

    const int  jj  = tid & 127;
    const int  grp = tid >> 7;
    const bool act = (jj < H);

    float acc[4][4];
    #pragma unroll
    for (int bl = 0; bl < 4; bl++)
        #pragma unroll
        for (int g = 0; g < 4; g++) acc[bl][g] = 0.f;

    for (int kt = 0; kt < 2; kt++) {
        __syncthreads();
        for (int i = tid; i < 40000; i += 256) {
            int g = i / 100, k = i - g * 100;
            wT[k * 400 + g] = wih1b[(size_t)g * 200 + kt * 100 + k];
        }
        __syncthreads();
        if (act) {
            #pragma unroll 2
            for (int k = 0; k < 100; k++) {
                const float* wr = wT + k * 400 + jj;
                float w0 = wr[0], w1 = wr[100], w2 = wr[200], w3 = wr[300];
                const float* hr = h0s + (kt * 100 + k) * 9 + grp * 4;
                #pragma unroll
                for (int bl = 0; bl < 4; bl++) {
                    float hv = hr[bl];
                    acc[bl][0] += w0 * hv; acc[bl][1] += w1 * hv;
                    acc[bl][2] += w2 * hv; acc[bl][3] += w3 * hv;
                }
            }
        }
    }
    if (act) {
        #pragma unroll
        for (int bl = 0; bl < 4; bl++) {
            int b = grp * 4 + bl;
            float iv = acc[bl][0] + bias[jj];
            float gv = acc[bl][2] + bias[200 + jj];
            float ov = acc[bl][3] + bias[300 + jj];
            float c = fsig(iv) * ftanh_(gv);     // c_prev = 0
            h1bs[b * 100 + jj] = fsig(ov) * ftanh_(c);
        }
    }
    __syncthreads();
    if (tid < 24) {
        int b = tid / 3, cls = tid - b * 3;
        float a = fcb[cls];
        const float* h1f = g_h1f + (size_t)(b0 + b) * 100;
        #pragma unroll 4
        for (int j = 0; j < 100; j++) {
            a += h1f[j]            * fcw[cls * 200 + j];
            a += h1bs[b * 100 + j] * fcw[cls * 200 + 100 + j];
        }
        lg[b * 3 + cls] = a;
    }
    __syncthreads();
    if (tid < 8) {
        int b = tid;
        float l0 = lg[b * 3], l1 = lg[b * 3 + 1], l2 = lg[b * 3 + 2];
        float m = fmaxf(l0, fmaxf(l1, l2));
        float e0 = __expf(l0 - m), e1 = __expf(l1 - m), e2 = __expf(l2 - m);
        float s = 1.0f / (e0 + e1 + e2);
        out[(b0 + b) * 3 + 0] = e0 * s;
        out[(b0 + b) * 3 + 1] = e1 * s;
        out[(b0 + b) * 3 + 2] = e2 * s;
    }
}

// ============================================================================
extern "C" void kernel_launch(void* const* d_in, const int* in_sizes, int n_in,
                              void* d_out, int out_size)
{
    (void)in_sizes; (void)n_in; (void)out_size;
    const float* x     = (const float*)d_in[0];
    const float* wih0f = (const float*)d_in[1];
    const float* whh0f = (const float*)d_in[2];
    const float* bih0f = (const float*)d_in[3];
    const float* bhh0f = (const float*)d_in[4];
    const float* wih0b = (const float*)d_in[5];
    const float* whh0b = (const float*)d_in[6];
    const float* bih0b = (const float*)d_in[7];
    const float* bhh0b = (const float*)d_in[8];
    const float* wih1f = (const float*)d_in[9];
    const float* whh1f = (const float*)d_in[10];
    const float* bih1f = (const float*)d_in[11];
    const float* bhh1f = (const float*)d_in[12];
    const float* wih1b = (const float*)d_in[13];
    const float* bih1b = (const float*)d_in[15];
    const float* bhh1b = (const float*)d_in[16];
    const float* fcw   = (const float*)d_in[17];
    const float* fcb   = (const float*)d_in[18];
    float* out = (float*)d_out;

    const int sm0 = L0_SMEMF * 4;
    const int sm1 = L1_SMEMF * 4;
    const int sm2 = FN_SMEMF * 4;
    cudaFuncSetAttribute(lstm_layer0,  cudaFuncAttributeMaxDynamicSharedMemorySize, sm0);
    cudaFuncSetAttribute(lstm_layer1f, cudaFuncAttributeMaxDynamicSharedMemorySize, sm1);
    cudaFuncSetAttribute(lstm_final,   cudaFuncAttributeMaxDynamicSharedMemorySize, sm2);

    lstm_layer0<<<128, 256, sm0>>>(x, wih0f, whh0f, bih0f, bhh0f,
                                      wih0b, whh0b, bih0b, bhh0b);
    gemm_xg1_kernel<<<dim3(1024, 5), 256>>>(wih1f, bih1f, bhh1f);
    lstm_layer1f<<<128, 256, sm1>>>(whh1f);
    lstm_final<<<128, 256, sm2>>>(wih1b, bih1b, bhh1b, fcw, fcb, out);
}